// round 1
// baseline (speedup 1.0000x reference)
#include <cuda_runtime.h>
#include <math.h>

#define K_CODES 1024
#define Dv      256
#define Nvec    65536
#define Sper    16384          // 16*32*32 spatial per batch
#define VT      128            // vectors per CTA
#define KT      64             // codes per smem tile
#define XS_STRIDE 260          // 260 % 32 == 4 -> conflict-free LDS.128
#define ZQ_ELEMS 16777216
#define FULL_OUT 16842754

__device__ float  g_ek2[K_CODES];
__device__ int    g_counts[K_CODES];
__device__ double g_loss;

// ---------------------------------------------------------------------------
// prep: per-code squared norms, zero histogram + loss accumulator
// ---------------------------------------------------------------------------
__global__ void prep_kernel(const float* __restrict__ emb) {
    int k = blockIdx.x * blockDim.x + threadIdx.x;
    if (k < K_CODES) {
        const float* row = emb + k * Dv;
        float s = 0.f;
        #pragma unroll 8
        for (int c = 0; c < Dv; ++c) { float e = row[c]; s += e * e; }
        g_ek2[k]    = s;
        g_counts[k] = 0;
    }
    if (blockIdx.x == 0 && threadIdx.x == 0) g_loss = 0.0;
}

// ---------------------------------------------------------------------------
// main: distances + argmin + gather + loss partial + histogram
// ---------------------------------------------------------------------------
__global__ __launch_bounds__(256, 1)
void vq_main_kernel(const float* __restrict__ z,
                    const float* __restrict__ emb,
                    float* __restrict__ out_z,
                    float* __restrict__ out_idx,
                    int write_aux) {
    extern __shared__ float sm[];
    float* xs   = sm;                          // [VT][XS_STRIDE] transposed-ish ([v][c])
    float* es   = xs + VT * XS_STRIDE;         // [KT][Dv]
    float* ek2s = es + KT * Dv;                // [KT]
    float* x2s  = ek2s + KT;                   // [VT]
    float* redv = x2s + VT;                    // [8][VT]
    int*   redi = (int*)(redv + 8 * VT);       // [8][VT]
    int*   ivec = redi + 8 * VT;               // [VT]
    float* rsum = redv;                        // reuse for loss reduction

    const int t   = threadIdx.x;
    const int cta = blockIdx.x;
    const int n0  = cta * VT;
    const int b   = n0 >> 14;                  // / Sper
    const int s0  = n0 & (Sper - 1);
    const float* zb = z + (size_t)b * Dv * Sper + s0;

    // ---- load X tile: xs[v][c] = z[b][c][s0+v] ----
    {
        int v = t & (VT - 1), ch = t >> 7;
        for (int c0 = 0; c0 < Dv; c0 += 2) {
            int c = c0 + ch;
            xs[v * XS_STRIDE + c] = zb[(size_t)c * Sper + v];
        }
    }
    __syncthreads();

    // ---- per-vector ||x||^2 (uniform shift across codes -> argmin-safe) ----
    if (t < VT) {
        const float* xr = xs + t * XS_STRIDE;
        float s = 0.f;
        #pragma unroll 8
        for (int c = 0; c < Dv; ++c) s += xr[c] * xr[c];
        x2s[t] = s;
    }
    __syncthreads();

    const int tv  = t & 31;    // vector column (lane)
    const int tkr = t >> 5;    // code row (uniform within warp)

    float x2r[4];
    #pragma unroll
    for (int i = 0; i < 4; ++i) x2r[i] = x2s[tv + 32 * i];

    float best[4]; int bidx[4];
    #pragma unroll
    for (int i = 0; i < 4; ++i) { best[i] = 3.4e38f; bidx[i] = 0; }

    for (int kt = 0; kt < K_CODES / KT; ++kt) {
        __syncthreads();  // previous tile fully consumed
        {
            float4* es4 = (float4*)es;
            const float4* emb4 = (const float4*)(emb + (size_t)kt * KT * Dv);
            for (int i = t; i < KT * Dv / 4; i += 256) es4[i] = emb4[i];
            if (t < KT) ek2s[t] = g_ek2[kt * KT + t];
        }
        __syncthreads();

        float acc[4][8];
        #pragma unroll
        for (int i = 0; i < 4; ++i)
            #pragma unroll
            for (int j = 0; j < 8; ++j) acc[i][j] = 0.f;

        const float4* es4 = (const float4*)es;
        #pragma unroll 2
        for (int c4 = 0; c4 < Dv / 4; ++c4) {
            float4 xv[4];
            #pragma unroll
            for (int i = 0; i < 4; ++i)
                xv[i] = *(const float4*)&xs[(tv + 32 * i) * XS_STRIDE + c4 * 4];
            #pragma unroll
            for (int j = 0; j < 8; ++j) {
                float4 e = es4[(tkr * 8 + j) * (Dv / 4) + c4];
                #pragma unroll
                for (int i = 0; i < 4; ++i) {
                    acc[i][j] += xv[i].x * e.x;
                    acc[i][j] += xv[i].y * e.y;
                    acc[i][j] += xv[i].z * e.z;
                    acc[i][j] += xv[i].w * e.w;
                }
            }
        }

        #pragma unroll
        for (int j = 0; j < 8; ++j) {
            int   kl = tkr * 8 + j;
            float e2 = ek2s[kl];
            int   kg = kt * KT + kl;
            #pragma unroll
            for (int i = 0; i < 4; ++i) {
                float tt = x2r[i] + e2;          // same quantization as reference
                float d  = tt - 2.0f * acc[i][j];
                if (d < best[i]) { best[i] = d; bidx[i] = kg; }  // k ascending -> first-min
            }
        }
    }

    // ---- cross-row argmin reduction (tie -> smaller index, matches jnp.argmin) ----
    #pragma unroll
    for (int i = 0; i < 4; ++i) {
        int v = tv + 32 * i;
        redv[tkr * VT + v] = best[i];
        redi[tkr * VT + v] = bidx[i];
    }
    __syncthreads();
    if (t < VT) {
        float bv = redv[t]; int bi = redi[t];
        #pragma unroll
        for (int r = 1; r < 8; ++r) {
            float xv_ = redv[r * VT + t]; int xi = redi[r * VT + t];
            if (xv_ < bv || (xv_ == bv && xi < bi)) { bv = xv_; bi = xi; }
        }
        ivec[t] = bi;
        atomicAdd(&g_counts[bi], 1);
        if (write_aux) out_idx[n0 + t] = (float)bi;
    }
    __syncthreads();

    // ---- gather z_q + commitment loss partial ----
    float lsum = 0.f;
    {
        int v = t & (VT - 1), ch = t >> 7;
        int kq = ivec[v];
        const float* er = emb + (size_t)kq * Dv;
        float* ob = out_z + (size_t)b * Dv * Sper + s0 + v;
        const float* xr = xs + v * XS_STRIDE;
        for (int c0 = 0; c0 < Dv; c0 += 2) {
            int c = c0 + ch;
            float e = er[c];
            ob[(size_t)c * Sper] = e;
            float dd = xr[c] - e;
            lsum += dd * dd;
        }
    }
    __syncthreads();   // redv no longer needed
    rsum[t] = lsum;
    __syncthreads();
    for (int off = 128; off > 0; off >>= 1) {
        if (t < off) rsum[t] += rsum[t + off];
        __syncthreads();
    }
    if (t == 0) atomicAdd(&g_loss, (double)rsum[0]);
}

// ---------------------------------------------------------------------------
// finalize: vq_loss + perplexity scalars
// ---------------------------------------------------------------------------
__global__ void finalize_kernel(float* __restrict__ out, int write_aux) {
    __shared__ double sh[256];
    int t = threadIdx.x;
    double s = 0.0;
    for (int k = t; k < K_CODES; k += 256) {
        float avg  = (float)g_counts[k] * (1.0f / 65536.0f);
        float term = avg * logf(avg + 1e-10f);
        s += (double)term;
    }
    sh[t] = s;
    __syncthreads();
    for (int off = 128; off > 0; off >>= 1) {
        if (t < off) sh[t] += sh[t + off];
        __syncthreads();
    }
    if (t == 0 && write_aux) {
        out[ZQ_ELEMS]            = 0.25f * (float)(g_loss / (double)ZQ_ELEMS);
        out[ZQ_ELEMS + 1 + Nvec] = expf(-(float)sh[0]);
    }
}

// ---------------------------------------------------------------------------
extern "C" void kernel_launch(void* const* d_in, const int* in_sizes, int n_in,
                              void* d_out, int out_size) {
    // defensive input-order resolution: z has 16,777,216 elems, embedding 262,144
    const float* z   = (const float*)d_in[0];
    const float* emb = (const float*)d_in[1];
    if (n_in >= 2 && in_sizes[0] == K_CODES * Dv && in_sizes[1] == ZQ_ELEMS) {
        z   = (const float*)d_in[1];
        emb = (const float*)d_in[0];
    }
    float* out = (float*)d_out;
    int aux = (out_size >= FULL_OUT) ? 1 : 0;
    float* out_idx = out + ZQ_ELEMS + 1;

    size_t smem = (size_t)(VT * XS_STRIDE + KT * Dv + KT + VT + 8 * VT) * sizeof(float)
                + (size_t)(8 * VT + VT) * sizeof(int);
    cudaFuncSetAttribute(vq_main_kernel,
                         cudaFuncAttributeMaxDynamicSharedMemorySize, (int)smem);

    prep_kernel<<<4, 256>>>(emb);
    vq_main_kernel<<<Nvec / VT, 256, smem>>>(z, emb, out, out_idx, aux);
    finalize_kernel<<<1, 256>>>(out, aux);
}